// round 9
// baseline (speedup 1.0000x reference)
#include <cuda_runtime.h>
#include <cuda_fp16.h>

#define Dn 24
#define Hn 96
#define Wn 192
#define HWn (Hn * Wn)          // 18432
#define Pn (Dn * HWn)          // 442368

typedef unsigned long long ull;
typedef unsigned int uint;

#define H2_ONES 0x3C003C00u    // half2 {1, 1}

// Scratch (device globals — allocation forbidden)
__device__ float g_q[Pn * 2];      // [p][2], q pre-scaled by log2(e)
__device__ float g_k[Pn * 2];      // [p][2]
__device__ uint  g_vh[Pn * 8];     // [p][8] half2: channels (2j, 2j+1)
__device__ float g_y[Pn * 16];     // intermediate image, [c][p]
__device__ float g_sH[Pn];
__device__ uint  g_oh[Pn * 8];     // unnormalized out_H, half2 channel pairs

// ---- helpers ---------------------------------------------------------------
__device__ __forceinline__ void F2(ull& d, ull a, ull b, ull c) {
    asm("fma.rn.f32x2 %0,%1,%2,%3;" : "=l"(d) : "l"(a), "l"(b), "l"(c));
}
__device__ __forceinline__ ull pack2(float lo, float hi) {
    ull r; asm("mov.b64 %0,{%1,%2};" : "=l"(r) : "f"(lo), "f"(hi)); return r;
}
__device__ __forceinline__ ull dup2(float v) { return pack2(v, v); }
__device__ __forceinline__ float2 unpack2(ull v) {
    float2 r; asm("mov.b64 {%0,%1},%2;" : "=f"(r.x), "=f"(r.y) : "l"(v)); return r;
}
__device__ __forceinline__ uint h2pack(float lo, float hi) {   // {lo, hi}
    uint u; asm("cvt.rn.f16x2.f32 %0,%1,%2;" : "=r"(u) : "f"(hi), "f"(lo)); return u;
}
__device__ __forceinline__ uint ex2h2(uint e) {                // 2 exps, 1 MUFU op
    uint r; asm("ex2.approx.f16x2 %0,%1;" : "=r"(r) : "r"(e)); return r;
}
__device__ __forceinline__ float2 h2unpack(uint u) {
    __half2 h = *reinterpret_cast<__half2*>(&u);
    return __half22float2(h);
}
__device__ __forceinline__ void mmah(float& d0, float& d1, float& d2, float& d3,
                                     uint a0, uint a1, uint b0) {
    asm("mma.sync.aligned.m16n8k8.row.col.f32.f16.f16.f32 "
        "{%0,%1,%2,%3},{%4,%5},{%6},{%0,%1,%2,%3};"
        : "+f"(d0), "+f"(d1), "+f"(d2), "+f"(d3)
        : "r"(a0), "r"(a1), "r"(b0));
}

#define L2E 1.44269504088896340736f

// ---------------------------------------------------------------------------
// QKV projection: 2 pixels/thread; v stored fp16 (half2 channel pairs).
// ---------------------------------------------------------------------------
__global__ __launch_bounds__(128) void qkv_kernel(const float* __restrict__ xin,
                           const float* __restrict__ qw, const float* __restrict__ qb,
                           const float* __restrict__ kw, const float* __restrict__ kb,
                           const float* __restrict__ vw, const float* __restrict__ vb)
{
    __shared__ float s_qw[32], s_kw[32], s_qb[2], s_kb[2];
    __shared__ ull s_vw[16][8];
    __shared__ ull s_vb[8];
    const float* x = xin ? xin : g_y;

    int t = threadIdx.x;
    {
        int c = t & 15, j = t >> 4;
        s_vw[c][j] = pack2(vw[(2 * j) * 16 + c], vw[(2 * j + 1) * 16 + c]);
    }
    if (t < 32)       s_qw[t]      = qw[t];
    else if (t < 64)  s_kw[t - 32] = kw[t - 32];
    else if (t < 66)  s_qb[t - 64] = qb[t - 64];
    else if (t < 68)  s_kb[t - 66] = kb[t - 66];
    else if (t < 76)  s_vb[t - 68] = pack2(vb[2 * (t - 68)], vb[2 * (t - 68) + 1]);
    __syncthreads();

    int p = blockIdx.x * 256 + 2 * t;   // 2 consecutive pixels

    float2 xv[16];
#pragma unroll
    for (int c = 0; c < 16; c++) xv[c] = *(const float2*)&x[c * Pn + p];

    float qa0 = s_qb[0], qa1 = s_qb[1], ka0 = s_kb[0], ka1 = s_kb[1];
    float qb0 = s_qb[0], qb1 = s_qb[1], kb0 = s_kb[0], kb1 = s_kb[1];
#pragma unroll
    for (int c = 0; c < 16; c++) {
        float wq0 = s_qw[c], wq1 = s_qw[16 + c], wk0 = s_kw[c], wk1 = s_kw[16 + c];
        qa0 = fmaf(wq0, xv[c].x, qa0);  qb0 = fmaf(wq0, xv[c].y, qb0);
        qa1 = fmaf(wq1, xv[c].x, qa1);  qb1 = fmaf(wq1, xv[c].y, qb1);
        ka0 = fmaf(wk0, xv[c].x, ka0);  kb0 = fmaf(wk0, xv[c].y, kb0);
        ka1 = fmaf(wk1, xv[c].x, ka1);  kb1 = fmaf(wk1, xv[c].y, kb1);
    }
    *(float4*)&g_q[p * 2] = make_float4(qa0 * L2E, qa1 * L2E, qb0 * L2E, qb1 * L2E);
    *(float4*)&g_k[p * 2] = make_float4(ka0, ka1, kb0, kb1);

    ull ava[8], avb[8];
#pragma unroll
    for (int j = 0; j < 8; j++) { ava[j] = s_vb[j]; avb[j] = s_vb[j]; }
#pragma unroll
    for (int c = 0; c < 16; c++) {
        ull xa = dup2(xv[c].x), xb = dup2(xv[c].y);
#pragma unroll
        for (int j = 0; j < 8; j++) {
            F2(ava[j], s_vw[c][j], xa, ava[j]);
            F2(avb[j], s_vw[c][j], xb, avb[j]);
        }
    }
    uint ha[8], hb[8];
#pragma unroll
    for (int j = 0; j < 8; j++) {
        float2 fa = unpack2(ava[j]), fb = unpack2(avb[j]);
        ha[j] = h2pack(fa.x, fa.y);
        hb[j] = h2pack(fb.x, fb.y);
    }
    uint4* vp = (uint4*)&g_vh[(size_t)p * 8];
    vp[0] = make_uint4(ha[0], ha[1], ha[2], ha[3]);
    vp[1] = make_uint4(ha[4], ha[5], ha[6], ha[7]);
    vp[2] = make_uint4(hb[0], hb[1], hb[2], hb[3]);
    vp[3] = make_uint4(hb[4], hb[5], hb[6], hb[7]);
}

// ---------------------------------------------------------------------------
// Pass A (fp16 MMA): 2 column lines per block, 12 warps (6 per column).
// exps via ex2.approx.f16x2; denominator via ones-column MMA; diag masked.
// ---------------------------------------------------------------------------
__global__ __launch_bounds__(384) void passA_kernel()
{
    __shared__ __align__(16) float2 s_q[2][96], s_k[2][96];
    __shared__ uint sVh[2][48 * 24];   // [col][rowpair*24 + ch]

    int d = blockIdx.y, t = threadIdx.x;
    int w2 = blockIdx.x * 2;

    if (t < 192) {
        int cc = t / 96, row = t % 96;
        int p = d * HWn + row * Wn + w2 + cc;
        s_q[cc][row] = ((const float2*)g_q)[p];
        s_k[cc][row] = ((const float2*)g_k)[p];
    } else {
        int t2 = t - 192;                 // 0..191
        int cc = t2 / 96, rem = t2 % 96;
        int rp = rem >> 1, hs = rem & 1;
        int pe = d * HWn + (2 * rp) * Wn + w2 + cc;
        int po = pe + Wn;
        uint4 e = *(const uint4*)&g_vh[(size_t)pe * 8 + hs * 4];
        uint4 o = *(const uint4*)&g_vh[(size_t)po * 8 + hs * 4];
        uint* dst = &sVh[cc][rp * 24 + hs * 8];
        dst[0] = __byte_perm(e.x, o.x, 0x5410); dst[1] = __byte_perm(e.x, o.x, 0x7632);
        dst[2] = __byte_perm(e.y, o.y, 0x5410); dst[3] = __byte_perm(e.y, o.y, 0x7632);
        dst[4] = __byte_perm(e.z, o.z, 0x5410); dst[5] = __byte_perm(e.z, o.z, 0x7632);
        dst[6] = __byte_perm(e.w, o.w, 0x5410); dst[7] = __byte_perm(e.w, o.w, 0x7632);
    }
    __syncthreads();

    int warp = t >> 5, lane = t & 31, g = lane >> 2, tig = lane & 3;
    int col = warp / 6, warpIn = warp % 6;
    int lineBase = d * HWn + w2 + col;
    int r0 = warpIn * 16 + g, r1 = r0 + 8;
    float2 q0 = s_q[col][r0], q1 = s_q[col][r1];

    float D0[4] = {0, 0, 0, 0};
    float D1[4] = {0, 0, 0, 0};
    float S[4]  = {0, 0, 0, 0};

#pragma unroll 2
    for (int kt = 0; kt < 12; kt++) {
        int c0 = kt * 8 + 2 * tig;
        float4 kk = *(const float4*)&s_k[col][c0];   // k[c0], k[c0+1]
        float e00 = fmaf(q0.y, kk.y, q0.x * kk.x);
        float e01 = fmaf(q0.y, kk.w, q0.x * kk.z);
        float e10 = fmaf(q1.y, kk.y, q1.x * kk.x);
        float e11 = fmaf(q1.y, kk.w, q1.x * kk.z);
        if (c0 == r0)     e00 = -1e4f;
        if (c0 + 1 == r0) e01 = -1e4f;
        if (c0 == r1)     e10 = -1e4f;
        if (c0 + 1 == r1) e11 = -1e4f;
        uint a0 = ex2h2(h2pack(e00, e01));
        uint a1 = ex2h2(h2pack(e10, e11));
        int rp = kt * 4 + tig;
        uint b0 = sVh[col][rp * 24 + g];
        uint b1 = sVh[col][rp * 24 + 8 + g];
        mmah(D0[0], D0[1], D0[2], D0[3], a0, a1, b0);
        mmah(D1[0], D1[1], D1[2], D1[3], a0, a1, b1);
        mmah(S[0],  S[1],  S[2],  S[3],  a0, a1, H2_ONES);
    }

    int p0 = lineBase + r0 * Wn, p1 = lineBase + r1 * Wn;
    if (tig == 0) { g_sH[p0] = S[0]; g_sH[p1] = S[2]; }
    g_oh[(size_t)p0 * 8 + tig]     = h2pack(D0[0], D0[1]);
    g_oh[(size_t)p1 * 8 + tig]     = h2pack(D0[2], D0[3]);
    g_oh[(size_t)p0 * 8 + 4 + tig] = h2pack(D1[0], D1[1]);
    g_oh[(size_t)p1 * 8 + 4 + tig] = h2pack(D1[2], D1[3]);
}

// ---------------------------------------------------------------------------
// Pass B (fp16 MMA): one row line per block, 12 warps. Combine + residual.
// ---------------------------------------------------------------------------
__global__ __launch_bounds__(384) void passB_kernel(const float* __restrict__ xin,
                                                    float* __restrict__ dst,
                                                    const float* __restrict__ gammap)
{
    __shared__ __align__(16) float2 s_q[192], s_k[192];
    __shared__ uint sVh[96 * 24];

    int d = blockIdx.y, h = blockIdx.x, t = threadIdx.x;
    int lineBase = d * HWn + h * Wn;
    const float* x = xin ? xin : g_y;
    float*       y = dst ? dst : g_y;

    if (t < 192) {
        int p = lineBase + t;
        s_q[t] = ((const float2*)g_q)[p];
        s_k[t] = ((const float2*)g_k)[p];
    } else {
        int t2 = t - 192;                 // 0..191
        int rp = t2 >> 1, hs = t2 & 1;
        int pe = lineBase + 2 * rp;
        uint4 e = *(const uint4*)&g_vh[(size_t)pe * 8 + hs * 4];
        uint4 o = *(const uint4*)&g_vh[(size_t)(pe + 1) * 8 + hs * 4];
        uint* dstp = &sVh[rp * 24 + hs * 8];
        dstp[0] = __byte_perm(e.x, o.x, 0x5410); dstp[1] = __byte_perm(e.x, o.x, 0x7632);
        dstp[2] = __byte_perm(e.y, o.y, 0x5410); dstp[3] = __byte_perm(e.y, o.y, 0x7632);
        dstp[4] = __byte_perm(e.z, o.z, 0x5410); dstp[5] = __byte_perm(e.z, o.z, 0x7632);
        dstp[6] = __byte_perm(e.w, o.w, 0x5410); dstp[7] = __byte_perm(e.w, o.w, 0x7632);
    }
    __syncthreads();

    int warp = t >> 5, lane = t & 31, g = lane >> 2, tig = lane & 3;
    int r0 = warp * 16 + g, r1 = r0 + 8;
    float2 q0 = s_q[r0], q1 = s_q[r1];

    float D0[4] = {0, 0, 0, 0};
    float D1[4] = {0, 0, 0, 0};
    float S[4]  = {0, 0, 0, 0};

#pragma unroll 2
    for (int kt = 0; kt < 24; kt++) {
        int c0 = kt * 8 + 2 * tig;
        float4 kk = *(const float4*)&s_k[c0];
        float e00 = fmaf(q0.y, kk.y, q0.x * kk.x);
        float e01 = fmaf(q0.y, kk.w, q0.x * kk.z);
        float e10 = fmaf(q1.y, kk.y, q1.x * kk.x);
        float e11 = fmaf(q1.y, kk.w, q1.x * kk.z);
        uint a0 = ex2h2(h2pack(e00, e01));
        uint a1 = ex2h2(h2pack(e10, e11));
        int rp = kt * 4 + tig;
        uint b0 = sVh[rp * 24 + g];
        uint b1 = sVh[rp * 24 + 8 + g];
        mmah(D0[0], D0[1], D0[2], D0[3], a0, a1, b0);
        mmah(D1[0], D1[1], D1[2], D1[3], a0, a1, b1);
        mmah(S[0],  S[1],  S[2],  S[3],  a0, a1, H2_ONES);
    }

    int p0 = lineBase + r0, p1 = lineBase + r1;
    float gamma = gammap[0];
    float inv0 = __fdividef(gamma, S[0] + g_sH[p0]);
    float inv1 = __fdividef(gamma, S[2] + g_sH[p1]);

    {
        float2 oh0 = h2unpack(g_oh[(size_t)p0 * 8 + tig]);
        float2 oh1 = h2unpack(g_oh[(size_t)p1 * 8 + tig]);
        int c = 2 * tig;
        y[c * Pn + p0]       = x[c * Pn + p0]       + (D0[0] + oh0.x) * inv0;
        y[(c + 1) * Pn + p0] = x[(c + 1) * Pn + p0] + (D0[1] + oh0.y) * inv0;
        y[c * Pn + p1]       = x[c * Pn + p1]       + (D0[2] + oh1.x) * inv1;
        y[(c + 1) * Pn + p1] = x[(c + 1) * Pn + p1] + (D0[3] + oh1.y) * inv1;
    }
    {
        float2 oh0 = h2unpack(g_oh[(size_t)p0 * 8 + 4 + tig]);
        float2 oh1 = h2unpack(g_oh[(size_t)p1 * 8 + 4 + tig]);
        int c = 8 + 2 * tig;
        y[c * Pn + p0]       = x[c * Pn + p0]       + (D1[0] + oh0.x) * inv0;
        y[(c + 1) * Pn + p0] = x[(c + 1) * Pn + p0] + (D1[1] + oh0.y) * inv0;
        y[c * Pn + p1]       = x[c * Pn + p1]       + (D1[2] + oh1.x) * inv1;
        y[(c + 1) * Pn + p1] = x[(c + 1) * Pn + p1] + (D1[3] + oh1.y) * inv1;
    }
}

// ---------------------------------------------------------------------------
extern "C" void kernel_launch(void* const* d_in, const int* in_sizes, int n_in,
                              void* d_out, int out_size)
{
    const float* x     = (const float*)d_in[0];
    const float* qw    = (const float*)d_in[1];
    const float* qb    = (const float*)d_in[2];
    const float* kw    = (const float*)d_in[3];
    const float* kb    = (const float*)d_in[4];
    const float* vw    = (const float*)d_in[5];
    const float* vb    = (const float*)d_in[6];
    const float* gamma = (const float*)d_in[7];
    float* out = (float*)d_out;

    dim3 gA(Wn / 2, Dn);   // 96 x 24 blocks, 384 threads
    dim3 gB(Hn, Dn);       // 96 x 24 blocks, 384 threads
    int qkvBlocks = Pn / 256;

    qkv_kernel<<<qkvBlocks, 128>>>(x, qw, qb, kw, kb, vw, vb);
    passA_kernel<<<gA, 384>>>();
    passB_kernel<<<gB, 384>>>(x, nullptr, gamma);

    qkv_kernel<<<qkvBlocks, 128>>>(nullptr, qw, qb, kw, kb, vw, vb);
    passA_kernel<<<gA, 384>>>();
    passB_kernel<<<gB, 384>>>(nullptr, out, gamma);
}